// round 16
// baseline (speedup 1.0000x reference)
#include <cuda_runtime.h>

#define SEQ   512
#define BATCH 2048
#define IND   4
#define H     50
#define NTHR  640                // 20 warps
#define HP    56                 // floats per h row: 50 h + 4 x + 2 pad = 28 pairs
#define NBLK  147                // 146 CTAs x 14  +  1 CTA x 4 (guarded) = 2048 batches
#define BT    14                 // single instantiation; runt CTA guards I/O via bmax

typedef unsigned long long ull;

// ---- packed dual-fp32 (sm_103a FFMA2 path, PTX-only) ----
__device__ __forceinline__ ull pack2(float lo, float hi) {
    ull r; asm("mov.b64 %0, {%1, %2};" : "=l"(r) : "f"(lo), "f"(hi)); return r;
}
__device__ __forceinline__ void unpack2(ull v, float& lo, float& hi) {
    asm("mov.b64 {%0, %1}, %2;" : "=f"(lo), "=f"(hi) : "l"(v));
}
__device__ __forceinline__ void fma2(ull& d, ull a, ull b) {
    asm("fma.rn.f32x2 %0, %1, %2, %0;" : "+l"(d) : "l"(a), "l"(b));
}
__device__ __forceinline__ ull add2(ull a, ull b) {
    ull r; asm("add.rn.f32x2 %0, %1, %2;" : "=l"(r) : "l"(a), "l"(b)); return r;
}
__device__ __forceinline__ float hsum(ull v) {
    float lo, hi; unpack2(v, lo, hi); return lo + hi;
}

// ---- fast activations (known-good: final rel_err ~1.5e-7) ----
__device__ __forceinline__ float sigf(float x) {
    return __fdividef(1.0f, 1.0f + __expf(-x));
}
__device__ __forceinline__ float tanh_fast(float x) {
    float ax = fabsf(x);
    float e  = __expf(-2.0f * ax);
    float t  = __fdividef(1.0f - e, 1.0f + e);
    return copysignf(t, x);
}

// GHALF: offset of the hi-half partial buffer; padded so GHALF % 16 == 8
// (keeps the two k-half STS.64 streams on disjoint bank-pair phases).
#define GS2 (BT + 1)             // pair-row stride in ull (conflict-free pad)
#define GH  (100 * GS2 + ((8 - 100 * GS2) & 15))
#define N1  (H * BT)             // cells per layer (700)

struct __align__(16) Smem {
    float h1s [BT][HP];      // layer1 h (+ x in slots 50..53, pads zero)
    float h1rs[BT][HP];      // relu(h1)
    float h2s [BT][HP];      // layer2 h
    float h2rs[BT][HP];      // relu(h2)
    ull   gp1 [2 * GH];      // L1 gates: entry r = pair(row r, row r+100); lo/hi k-half
    ull   gp2a[2 * GH];      // L2 w_ih2 part
    ull   gp2b[2 * GH];      // L2 w_hh2 part
    float xs[BT][IND];       // staged x(t+1)
    float wfcs[52];
    float bfcs;
};

// cells: unit u in [0,50). Pair entry u holds gates (i_u, g_u); entry u+50 holds (f_u, o_u).
__device__ __forceinline__ void l1_cell(Smem* S, int u, int b, float& c) {
    ull ig = add2(S->gp1[      u  * GS2 + b], S->gp1[GH +       u  * GS2 + b]);
    ull fo = add2(S->gp1[(u + 50) * GS2 + b], S->gp1[GH + (u + 50) * GS2 + b]);
    float gi, gg, gf, go;
    unpack2(ig, gi, gg);
    unpack2(fo, gf, go);
    float cn = sigf(gf) * c + sigf(gi) * tanh_fast(gg);
    c = cn;
    float hv = sigf(go) * tanh_fast(cn);
    S->h1s[b][u]  = hv;
    S->h1rs[b][u] = fmaxf(hv, 0.f);
}

__device__ __forceinline__ void l2_cell(Smem* S, int u, int b, float& c) {
    ull ig = add2(add2(S->gp2a[      u  * GS2 + b], S->gp2a[GH +       u  * GS2 + b]),
                  add2(S->gp2b[      u  * GS2 + b], S->gp2b[GH +       u  * GS2 + b]));
    ull fo = add2(add2(S->gp2a[(u + 50) * GS2 + b], S->gp2a[GH + (u + 50) * GS2 + b]),
                  add2(S->gp2b[(u + 50) * GS2 + b], S->gp2b[GH + (u + 50) * GS2 + b]));
    float gi, gg, gf, go;
    unpack2(ig, gi, gg);
    unpack2(fo, gf, go);
    float cn = sigf(gf) * c + sigf(gi) * tanh_fast(gg);
    c = cn;
    float hv = sigf(go) * tanh_fast(cn);
    S->h2s[b][u]  = hv;
    S->h2rs[b][u] = fmaxf(hv, 0.f);
}

__global__ __launch_bounds__(NTHR, 1)
void lstm_fused_kernel(
    const float* __restrict__ x,
    const float* __restrict__ w_ih1, const float* __restrict__ w_hh1,
    const float* __restrict__ b_ih1, const float* __restrict__ b_hh1,
    const float* __restrict__ w_ih2, const float* __restrict__ w_hh2,
    const float* __restrict__ b_ih2, const float* __restrict__ b_hh2,
    const float* __restrict__ w_fc,  const float* __restrict__ b_fc,
    float* __restrict__ out)
{
    extern __shared__ char smem_raw[];
    Smem* S = (Smem*)smem_raw;

    const int tid  = threadIdx.x;
    const int B0   = blockIdx.x * BT;
    const int bmax = min(BT, BATCH - B0);          // runt CTA: only 4 real batches

    // ---- init: zero h arrays (incl pads) ----
    for (int i = tid; i < 4 * BT * HP; i += NTHR)
        ((float*)S->h1s)[i] = 0.f;
    if (tid < 52)  S->wfcs[tid] = (tid < H) ? w_fc[tid] : 0.f;
    if (tid == 0)  S->bfcs = b_fc[0];
    __syncthreads();
    if (tid < BT * IND) {                          // x(0) into h1 row slots
        int b = tid >> 2, d = tid & 3;
        if (b < bmax) S->h1s[b][H + d] = x[(B0 + b) * IND + d];
    }

    // ---- per-thread packed weights: 2 rows x half-k (R12-proven mapping) ----
    ull w2a[14], w2b[14];
#pragma unroll
    for (int q = 0; q < 14; q++) { w2a[q] = 0ULL; w2b[q] = 0ULL; }
    float br0 = 0.f, br1 = 0.f;
    const float* hb = &S->h1s[0][0];
    ull* gdst = S->gp1;
    int  hoff = 0;

    if (tid < 600) {
        const int band = tid / 200;
        const int u    = tid - band * 200;
        const int half = u & 1;                    // R12 mapping (do NOT change)
        const int r    = u >> 1;                   // pair index 0..99
        hoff = half * 28;
        const float* wsrc = (band == 0) ? w_hh1 : (band == 1) ? w_ih2 : w_hh2;
#pragma unroll
        for (int q = 0; q < 14; q++) {
            const int P = 14 * half + q;
            float alo = 0.f, ahi = 0.f, blo = 0.f, bhi = 0.f;
            if (P < 25) {
                alo = wsrc[(r      ) * H + 2 * P]; ahi = wsrc[(r      ) * H + 2 * P + 1];
                blo = wsrc[(r + 100) * H + 2 * P]; bhi = wsrc[(r + 100) * H + 2 * P + 1];
            } else if (P < 27 && band == 0) {
                const int d = (P - 25) * 2;
                alo = w_ih1[(r      ) * IND + d];  ahi = w_ih1[(r      ) * IND + d + 1];
                blo = w_ih1[(r + 100) * IND + d];  bhi = w_ih1[(r + 100) * IND + d + 1];
            }
            w2a[q] = pack2(alo, ahi);
            w2b[q] = pack2(blo, bhi);
        }
        if (half == 0) {
            if (band == 0) { br0 = b_ih1[r] + b_hh1[r]; br1 = b_ih1[r + 100] + b_hh1[r + 100]; }
            if (band == 1) { br0 = b_ih2[r] + b_hh2[r]; br1 = b_ih2[r + 100] + b_hh2[r + 100]; }
        }
        if      (band == 0) { hb = &S->h1s [0][0]; gdst = S->gp1  + half * GH + r * GS2; }
        else if (band == 1) { hb = &S->h1rs[0][0]; gdst = S->gp2a + half * GH + r * GS2; }
        else                { hb = &S->h2s [0][0]; gdst = S->gp2b + half * GH + r * GS2; }
    }

    // ---- phase-B cell map, t-invariant (was div/mod by 14 EVERY step) ----
    // j0: c = tid        in [0,640)    -> always L1 (c < N1=700)
    // j1: c = tid+640    in [640,1280) -> L1 iff tid < 60, else L2 r=c-700
    // j2: c = tid+1280   in [1280,1920)-> L2 iff tid < 120 (r=580..699), else idle
    const int  c0u = tid / BT,            c0b = tid % BT;
    const bool j1_l1 = (tid < N1 - NTHR);                   // tid < 60
    const int  r1  = j1_l1 ? (tid + NTHR) : (tid + NTHR - N1);
    const int  c1u = r1 / BT,             c1b = r1 % BT;
    const bool j2_act = (tid < 2 * N1 - 2 * NTHR);          // tid < 120
    const int  r2  = j2_act ? (tid + 2 * NTHR - N1) : 0;    // 580..699
    const int  c2u = r2 / BT,             c2b = r2 % BT;

    float cst[3];
#pragma unroll
    for (int j = 0; j < 3; j++) cst[j] = 0.f;
    __syncthreads();

    // Pipeline: A(t): L1-gates(t) || L2-gates(t-1) || FC(t-2) || prefetch x(t+1)
    //           B(t): L1-cells(t) || L2-cells(t-1) || copy x(t+1) into h1 slots
    for (int t = 0; t <= SEQ + 1; ++t) {
        const bool l1_act = (t < SEQ);
        const bool l2_act = (t >= 1 && t <= SEQ);
        // ================= phase A =================
        if (tid < 600) {
            const bool act = (tid < 200) ? l1_act : l2_act;
            if (act) {
#pragma unroll 2
                for (int b = 0; b < BT; b++) {
                    const ulonglong2* hp = (const ulonglong2*)(hb + b * HP + hoff);
                    ull a0 = 0ULL, a1 = 0ULL, c0 = 0ULL, c1 = 0ULL;
#pragma unroll
                    for (int q = 0; q < 7; q++) {  // 7 LDS.128 broadcast
                        ulonglong2 hv = hp[q];
                        fma2(a0, w2a[2 * q],     hv.x);
                        fma2(a1, w2a[2 * q + 1], hv.y);
                        fma2(c0, w2b[2 * q],     hv.x);
                        fma2(c1, w2b[2 * q + 1], hv.y);
                    }
                    float p0 = hsum(add2(a0, a1)) + br0;   // row r
                    float p1 = hsum(add2(c0, c1)) + br1;   // row r+100
                    gdst[b] = pack2(p0, p1);               // STS.64, conflict-free
                }
            }
        } else if (tid >= 600 && tid < 600 + BT) {
            if (t >= 2) {                               // FC for step t-2
                const int b = tid - 600;
                if (b < bmax) {
                    float a0 = S->bfcs, a1 = 0.f, a2 = 0.f, a3 = 0.f;
#pragma unroll
                    for (int q = 0; q < 13; q++) {
                        float4 wv = *(const float4*)&S->wfcs[4 * q];
                        float4 hv = *(const float4*)&S->h2rs[b][4 * q];
                        a0 += wv.x * hv.x; a1 += wv.y * hv.y;
                        a2 += wv.z * hv.z; a3 += wv.w * hv.w;
                    }
                    out[(t - 2) * BATCH + B0 + b] = (a0 + a1) + (a2 + a3);
                }
            }
        } else if (tid >= 624 && tid < 632) {
            if (t + 1 < SEQ) {                          // prefetch x(t+1) -> xs
                const int i = tid - 624;                // 0..7
#pragma unroll
                for (int j = 0; j < 7; j++) {
                    int idx = i * 7 + j;
                    if (idx < IND * BT) {
                        int b = idx >> 2, d = idx & 3;
                        if (b < bmax)
                            S->xs[b][d] = x[((t + 1) * BATCH + B0 + b) * IND + d];
                    }
                }
            }
        }
        __syncthreads();

        // ================= phase B ================= (precomputed cell map)
        if (l1_act) l1_cell(S, c0u, c0b, cst[0]);               // j0: all L1
        if (j1_l1) {                                            // j1
            if (l1_act) l1_cell(S, c1u, c1b, cst[1]);
        } else {
            if (l2_act) l2_cell(S, c1u, c1b, cst[1]);
        }
        if (j2_act && l2_act) l2_cell(S, c2u, c2b, cst[2]);     // j2 tail
        if (tid >= 320 && tid < 320 + IND * BT) {               // x(t+1) into h1 slots
            if (t + 1 < SEQ) {
                int i2 = tid - 320;
                int b = i2 >> 2, d = i2 & 3;
                if (b < bmax) S->h1s[b][H + d] = S->xs[b][d];
            }
        }
        __syncthreads();
    }
}

extern "C" void kernel_launch(void* const* d_in, const int* in_sizes, int n_in,
                              void* d_out, int out_size)
{
    const float* x     = (const float*)d_in[0];
    const float* w_ih1 = (const float*)d_in[1];
    const float* w_hh1 = (const float*)d_in[2];
    const float* b_ih1 = (const float*)d_in[3];
    const float* b_hh1 = (const float*)d_in[4];
    const float* w_ih2 = (const float*)d_in[5];
    const float* w_hh2 = (const float*)d_in[6];
    const float* b_ih2 = (const float*)d_in[7];
    const float* b_hh2 = (const float*)d_in[8];
    const float* w_fc  = (const float*)d_in[9];
    const float* b_fc  = (const float*)d_in[10];
    float* out = (float*)d_out;

    const int smem = (int)sizeof(Smem);
    cudaFuncSetAttribute(lstm_fused_kernel,
                         cudaFuncAttributeMaxDynamicSharedMemorySize, smem);
    lstm_fused_kernel<<<NBLK, NTHR, smem>>>(
        x, w_ih1, w_hh1, b_ih1, b_hh1,
        w_ih2, w_hh2, b_ih2, b_hh2, w_fc, b_fc, out);
}

// round 17
// speedup vs baseline: 1.0287x; 1.0287x over previous
#include <cuda_runtime.h>

#define SEQ   512
#define BATCH 2048
#define IND   4
#define H     50
#define NTHR  640                // 20 warps
#define HP    56                 // floats per h row: 50 h + 4 x + 2 pad = 28 pairs
#define NBLK  147                // 146 CTAs x 14  +  1 CTA x 4 (guarded) = 2048 batches
#define BT    14
#define QPAD  6                  // quarter dim padded 4 -> 6 (bank spread)
#define SLTW  (BT * QPAD)        // 84 ull per gate-pair slot
#define FOOFF (50 * SLTW)        // fo slots start 50 slots in (4200 ull)
#define GQSZ  (100 * SLTW)       // 8400 ull per matmul buffer
#define N1    (H * BT)           // cells per layer (700)

typedef unsigned long long ull;

// ---- packed dual-fp32 (sm_103a FFMA2 path, PTX-only) ----
__device__ __forceinline__ ull pack2(float lo, float hi) {
    ull r; asm("mov.b64 %0, {%1, %2};" : "=l"(r) : "f"(lo), "f"(hi)); return r;
}
__device__ __forceinline__ void unpack2(ull v, float& lo, float& hi) {
    asm("mov.b64 {%0, %1}, %2;" : "=f"(lo), "=f"(hi) : "l"(v));
}
__device__ __forceinline__ void fma2(ull& d, ull a, ull b) {
    asm("fma.rn.f32x2 %0, %1, %2, %0;" : "+l"(d) : "l"(a), "l"(b));
}
__device__ __forceinline__ ull add2(ull a, ull b) {
    ull r; asm("add.rn.f32x2 %0, %1, %2;" : "=l"(r) : "l"(a), "l"(b)); return r;
}
__device__ __forceinline__ float hsum(ull v) {
    float lo, hi; unpack2(v, lo, hi); return lo + hi;
}

// ---- fast activations (known-good accuracy class ~1.5e-7 final) ----
__device__ __forceinline__ float sigf(float x) {
    return __fdividef(1.0f, 1.0f + __expf(-x));
}
__device__ __forceinline__ float tanh_fast(float x) {
    float ax = fabsf(x);
    float e  = __expf(-2.0f * ax);
    float t  = __fdividef(1.0f - e, 1.0f + e);
    return copysignf(t, x);
}

struct __align__(16) Smem {
    float h1s [BT][HP];      // layer1 h (+ x in slots 50..53, pads zero)
    float h1rs[BT][HP];      // relu(h1)
    float h2s [BT][HP];      // layer2 h
    float h2rs[BT][HP];      // relu(h2)
    // quarter-partial gate buffers, layout [slot][b][qt(6)]:
    //   slot u      = (i,g) pair of unit u   (rows u, u+100)
    //   slot u+50   = (f,o) pair of unit u   (rows u+50, u+150)
    ull   gq1 [GQSZ];        // L1 gates (bias folded, qt0 threads)
    ull   gq2a[GQSZ];        // L2 w_ih2 part (bias folded, qt0 threads)
    ull   gq2b[GQSZ];        // L2 w_hh2 part
    float xs[BT][IND];       // staged x(t+1)
    float wfcs[52];
    float bfcs;
};

// sum 4 quarter-partials of one gate-pair slot: 2 contiguous LDS.128
__device__ __forceinline__ ull qsum(const ull* base) {
    const ulonglong2* p = (const ulonglong2*)base;
    ulonglong2 v01 = p[0], v23 = p[1];
    return add2(add2(v01.x, v01.y), add2(v23.x, v23.y));
}

__device__ __forceinline__ void l1_cell(Smem* S, int u, int b, float& c) {
    ull ig = qsum(&S->gq1[      u  * SLTW + b * QPAD]);
    ull fo = qsum(&S->gq1[(u + 50) * SLTW + b * QPAD]);
    float gi, gg, gf, go;
    unpack2(ig, gi, gg);
    unpack2(fo, gf, go);
    float cn = sigf(gf) * c + sigf(gi) * tanh_fast(gg);
    c = cn;
    float hv = sigf(go) * tanh_fast(cn);
    S->h1s[b][u]  = hv;
    S->h1rs[b][u] = fmaxf(hv, 0.f);
}

__device__ __forceinline__ void l2_cell(Smem* S, int u, int b, float& c) {
    ull ig = add2(qsum(&S->gq2a[      u  * SLTW + b * QPAD]),
                  qsum(&S->gq2b[      u  * SLTW + b * QPAD]));
    ull fo = add2(qsum(&S->gq2a[(u + 50) * SLTW + b * QPAD]),
                  qsum(&S->gq2b[(u + 50) * SLTW + b * QPAD]));
    float gi, gg, gf, go;
    unpack2(ig, gi, gg);
    unpack2(fo, gf, go);
    float cn = sigf(gf) * c + sigf(gi) * tanh_fast(gg);
    c = cn;
    float hv = sigf(go) * tanh_fast(cn);
    S->h2s[b][u]  = hv;
    S->h2rs[b][u] = fmaxf(hv, 0.f);
}

__global__ __launch_bounds__(NTHR, 1)
void lstm_fused_kernel(
    const float* __restrict__ x,
    const float* __restrict__ w_ih1, const float* __restrict__ w_hh1,
    const float* __restrict__ b_ih1, const float* __restrict__ b_hh1,
    const float* __restrict__ w_ih2, const float* __restrict__ w_hh2,
    const float* __restrict__ b_ih2, const float* __restrict__ b_hh2,
    const float* __restrict__ w_fc,  const float* __restrict__ b_fc,
    float* __restrict__ out)
{
    extern __shared__ char smem_raw[];
    Smem* S = (Smem*)smem_raw;

    const int tid  = threadIdx.x;
    const int B0   = blockIdx.x * BT;
    const int bmax = min(BT, BATCH - B0);          // runt CTA: only 4 real batches

    // ---- init: zero h arrays (incl pads) ----
    for (int i = tid; i < 4 * BT * HP; i += NTHR)
        ((float*)S->h1s)[i] = 0.f;
    if (tid < 52)  S->wfcs[tid] = (tid < H) ? w_fc[tid] : 0.f;
    if (tid == 0)  S->bfcs = b_fc[0];
    __syncthreads();
    if (tid < BT * IND) {                          // x(0) into h1 row slots
        int b = tid >> 2, d = tid & 3;
        if (b < bmax) S->h1s[b][H + d] = x[(B0 + b) * IND + d];
    }

    // ---- per-thread packed weights: 4 gate rows x quarter-k ----
    // tid<600: band = tid/200, u = tid%200, unit r = u>>2, quarter qt = u&3.
    // Thread owns rows r, r+50, r+100, r+150 (gates i,f,g,o of unit r),
    // k-pairs P = 7*qt .. 7*qt+6.  28 weight ulls — same regs as before,
    // but loads per batch drop to 7 LDS.64 (half the wavefronts).
    ull w4[4][7];
#pragma unroll
    for (int g = 0; g < 4; g++)
#pragma unroll
        for (int q = 0; q < 7; q++) w4[g][q] = 0ULL;
    float bi = 0.f, bf_ = 0.f, bg = 0.f, bo = 0.f; // bias, qt0 threads only
    const float* hb = &S->h1s[0][0];
    ull* gdst = S->gq1;
    int  qt = 0;

    if (tid < 600) {
        const int band = tid / 200;
        const int u    = tid - band * 200;
        const int r    = u >> 2;                   // unit 0..49
        qt             = u & 3;                    // quarter 0..3 (interleaved)
        const float* wsrc = (band == 0) ? w_hh1 : (band == 1) ? w_ih2 : w_hh2;
#pragma unroll
        for (int q = 0; q < 7; q++) {
            const int P = 7 * qt + q;              // global pair 0..27
#pragma unroll
            for (int g = 0; g < 4; g++) {
                const int row = r + 50 * g;
                float lo = 0.f, hi = 0.f;
                if (P < 25) {
                    lo = wsrc[row * H + 2 * P]; hi = wsrc[row * H + 2 * P + 1];
                } else if (P < 27 && band == 0) {  // x slots (pairs 25,26)
                    const int d = (P - 25) * 2;
                    lo = w_ih1[row * IND + d];  hi = w_ih1[row * IND + d + 1];
                }
                w4[g][q] = pack2(lo, hi);
            }
        }
        if (qt == 0) {
            if (band == 0) {
                bi  = b_ih1[r      ] + b_hh1[r      ];
                bf_ = b_ih1[r +  50] + b_hh1[r +  50];
                bg  = b_ih1[r + 100] + b_hh1[r + 100];
                bo  = b_ih1[r + 150] + b_hh1[r + 150];
            } else if (band == 1) {
                bi  = b_ih2[r      ] + b_hh2[r      ];
                bf_ = b_ih2[r +  50] + b_hh2[r +  50];
                bg  = b_ih2[r + 100] + b_hh2[r + 100];
                bo  = b_ih2[r + 150] + b_hh2[r + 150];
            }
        }
        if      (band == 0) { hb = &S->h1s [0][0]; gdst = S->gq1  + r * SLTW + qt; }
        else if (band == 1) { hb = &S->h1rs[0][0]; gdst = S->gq2a + r * SLTW + qt; }
        else                { hb = &S->h2s [0][0]; gdst = S->gq2b + r * SLTW + qt; }
    }

    // ---- phase-B cell map, t-invariant ----
    const int  c0u = tid / BT,            c0b = tid % BT;
    const bool j1_l1 = (tid < N1 - NTHR);                   // tid < 60
    const int  r1  = j1_l1 ? (tid + NTHR) : (tid + NTHR - N1);
    const int  c1u = r1 / BT,             c1b = r1 % BT;
    const bool j2_act = (tid < 2 * N1 - 2 * NTHR);          // tid < 120
    const int  r2  = j2_act ? (tid + 2 * NTHR - N1) : 0;    // 580..699
    const int  c2u = r2 / BT,             c2b = r2 % BT;

    float cst[3];
#pragma unroll
    for (int j = 0; j < 3; j++) cst[j] = 0.f;
    __syncthreads();

    // Pipeline: A(t): L1-gates(t) || L2-gates(t-1) || FC(t-2) || prefetch x(t+1)
    //           B(t): L1-cells(t) || L2-cells(t-1) || copy x(t+1) into h1 slots
    for (int t = 0; t <= SEQ + 1; ++t) {
        const bool l1_act = (t < SEQ);
        const bool l2_act = (t >= 1 && t <= SEQ);
        // ================= phase A =================
        if (tid < 600) {
            const bool act = (tid < 200) ? l1_act : l2_act;
            if (act) {
#pragma unroll 2
                for (int b = 0; b < BT; b++) {
                    const ull* hp = (const ull*)(hb + b * HP) + 7 * qt;
                    ull a0 = 0ULL, a1 = 0ULL, a2 = 0ULL, a3 = 0ULL;
#pragma unroll
                    for (int q = 0; q < 7; q++) {  // 7 LDS.64 broadcast
                        ull hv = hp[q];
                        fma2(a0, w4[0][q], hv);    // gate i row
                        fma2(a1, w4[1][q], hv);    // gate f row
                        fma2(a2, w4[2][q], hv);    // gate g row
                        fma2(a3, w4[3][q], hv);    // gate o row
                    }
                    float pi = hsum(a0) + bi;
                    float pf = hsum(a1) + bf_;
                    float pg = hsum(a2) + bg;
                    float po = hsum(a3) + bo;
                    gdst[        b * QPAD] = pack2(pi, pg);   // (i,g) slot, my qt
                    gdst[FOOFF + b * QPAD] = pack2(pf, po);   // (f,o) slot
                }
            }
        } else if (tid >= 600 && tid < 600 + BT) {
            if (t >= 2) {                               // FC for step t-2
                const int b = tid - 600;
                if (b < bmax) {
                    float a0 = S->bfcs, a1 = 0.f, a2 = 0.f, a3 = 0.f;
#pragma unroll
                    for (int q = 0; q < 13; q++) {
                        float4 wv = *(const float4*)&S->wfcs[4 * q];
                        float4 hv = *(const float4*)&S->h2rs[b][4 * q];
                        a0 += wv.x * hv.x; a1 += wv.y * hv.y;
                        a2 += wv.z * hv.z; a3 += wv.w * hv.w;
                    }
                    out[(t - 2) * BATCH + B0 + b] = (a0 + a1) + (a2 + a3);
                }
            }
        } else if (tid >= 624 && tid < 632) {
            if (t + 1 < SEQ) {                          // prefetch x(t+1) -> xs
                const int i = tid - 624;                // 0..7
#pragma unroll
                for (int j = 0; j < 7; j++) {
                    int idx = i * 7 + j;
                    if (idx < IND * BT) {
                        int b = idx >> 2, d = idx & 3;
                        if (b < bmax)
                            S->xs[b][d] = x[((t + 1) * BATCH + B0 + b) * IND + d];
                    }
                }
            }
        }
        __syncthreads();

        // ================= phase B ================= (precomputed cell map)
        if (l1_act) l1_cell(S, c0u, c0b, cst[0]);               // j0: all L1
        if (j1_l1) {                                            // j1
            if (l1_act) l1_cell(S, c1u, c1b, cst[1]);
        } else {
            if (l2_act) l2_cell(S, c1u, c1b, cst[1]);
        }
        if (j2_act && l2_act) l2_cell(S, c2u, c2b, cst[2]);     // j2 tail
        if (tid >= 320 && tid < 320 + IND * BT) {               // x(t+1) into h1 slots
            if (t + 1 < SEQ) {
                int i2 = tid - 320;
                int b = i2 >> 2, d = i2 & 3;
                if (b < bmax) S->h1s[b][H + d] = S->xs[b][d];
            }
        }
        __syncthreads();
    }
}

extern "C" void kernel_launch(void* const* d_in, const int* in_sizes, int n_in,
                              void* d_out, int out_size)
{
    const float* x     = (const float*)d_in[0];
    const float* w_ih1 = (const float*)d_in[1];
    const float* w_hh1 = (const float*)d_in[2];
    const float* b_ih1 = (const float*)d_in[3];
    const float* b_hh1 = (const float*)d_in[4];
    const float* w_ih2 = (const float*)d_in[5];
    const float* w_hh2 = (const float*)d_in[6];
    const float* b_ih2 = (const float*)d_in[7];
    const float* b_hh2 = (const float*)d_in[8];
    const float* w_fc  = (const float*)d_in[9];
    const float* b_fc  = (const float*)d_in[10];
    float* out = (float*)d_out;

    const int smem = (int)sizeof(Smem);               // ~210 KB, <= 227 KB cap
    cudaFuncSetAttribute(lstm_fused_kernel,
                         cudaFuncAttributeMaxDynamicSharedMemorySize, smem);
    lstm_fused_kernel<<<NBLK, NTHR, smem>>>(
        x, w_ih1, w_hh1, b_ih1, b_hh1,
        w_ih2, w_hh2, b_ih2, b_hh2, w_fc, b_fc, out);
}